// round 6
// baseline (speedup 1.0000x reference)
#include <cuda_runtime.h>
#include <cstdint>
#include <math.h>

#define BATCH 4
#define SEQ   2048
#define DIM   1024
#define MTOT  (BATCH*SEQ)

// Scratch (__device__ globals; allocation-free rule)
__device__ float g_QKV[(size_t)MTOT*3*DIM];     // 100 MB ([8192][3072]: Q|K|V)
__device__ float g_VT [(size_t)BATCH*SEQ*DIM];  // 32 MB  (V^T per batch: [D][S])
__device__ float g_P  [(size_t)BATCH*SEQ*SEQ];  // 64 MB
__device__ float g_X  [(size_t)MTOT*DIM];       // 32 MB  (x rounded to tf32)
__device__ float g_W  [(size_t)3*DIM*DIM];      // 12 MB  (Wq|Wk|Wv rounded, row-concat)
__device__ float g_B  [3*DIM];                  // packed bias

// ---------------------------------------------------------------------------
__device__ __forceinline__ uint32_t smem_u32(const void* p){
    uint32_t a;
    asm("{ .reg .u64 t; cvta.to.shared.u64 t, %1; cvt.u32.u64 %0, t; }"
        : "=r"(a) : "l"(p));
    return a;
}
#define SW128(o) ((o) ^ (((o) >> 3) & 0x70))

__device__ __forceinline__ void cp16(uint32_t s, const void* g){
    asm volatile("cp.async.cg.shared.global [%0], [%1], 16;" :: "r"(s), "l"(g));
}
__device__ __forceinline__ float tf32r(float f){
    uint32_t u;
    asm("cvt.rna.tf32.f32 %0, %1;" : "=r"(u) : "f"(f));
    return __uint_as_float(u);
}

// ---------------------------------------------------------------------------
__global__ __launch_bounds__(256)
void round_tf32(const float* __restrict__ src, float* __restrict__ dst, int n4)
{
    int i = blockIdx.x * 256 + threadIdx.x;
    if (i >= n4) return;
    float4 v = ((const float4*)src)[i];
    v.x = tf32r(v.x); v.y = tf32r(v.y); v.z = tf32r(v.z); v.w = tf32r(v.w);
    ((float4*)dst)[i] = v;
}

__global__ __launch_bounds__(256)
void pack_bias(const float* __restrict__ bq, const float* __restrict__ bk,
               const float* __restrict__ bv, float* __restrict__ b)
{
    int i = blockIdx.x * 256 + threadIdx.x;
    if (i < DIM){ b[i] = bq[i]; b[DIM + i] = bk[i]; b[2*DIM + i] = bv[i]; }
}

// ---------------------------------------------------------------------------
// tf32 HMMA GEMM-NT: C[m,n] = scale * sum_k A[m,k]*B[n,k] (+ bias[n])
// Operands pre-rounded to tf32. CTA tile 128x256, BK=32, 3-stage cp.async,
// 512 threads (warp grid 4M x 4N, each 32x64).
// mode: 0 plain; 1 causal scores (skip tiles fully above diagonal);
//       2 PV (truncate K at (by+1)*128).
// ---------------------------------------------------------------------------
#define STG_BYTES 49152u   // A 16KB + B 32KB per stage

__global__ __launch_bounds__(512, 1)
void gemm_mma(const float* __restrict__ A, const float* __restrict__ B,
              const float* __restrict__ bias, float* __restrict__ C,
              int K, int lda, int ldb, int ldc,
              long sA, long sB, long sC, float scale, int mode, int rnd)
{
    const int bx = blockIdx.x, by = blockIdx.y, bz = blockIdx.z;
    if (mode == 1 && bx * 256 > by * 128 + 127) return;
    A += (size_t)bz * sA; B += (size_t)bz * sB; C += (size_t)bz * sC;

    const int Keff = (mode == 2) ? min(K, (by + 1) * 128) : K;
    const int nch  = Keff >> 5;

    extern __shared__ char dsm[];
    const uint32_t base = (smem_u32(dsm) + 1023) & ~1023u;
    const int tid = threadIdx.x, lane = tid & 31, wid = tid >> 5;
    const int wm = wid & 3, wn = wid >> 2;     // 4 (M) x 4 (N)

    const float* Ab = A + (size_t)(by * 128) * lda;
    const float* Bb = B + (size_t)(bx * 256) * ldb;

    // A: 128 rows x 128B; B: 256 rows x 128B; SW128 swizzled
    auto load_A = [&](int k0, uint32_t sb){
        #pragma unroll
        for (int it = 0; it < 2; it++){
            int idx = tid + it * 512;
            int r = idx >> 3, c4 = idx & 7;
            uint32_t off = (uint32_t)(r * 128 + c4 * 16);
            cp16(sb + SW128(off), Ab + (size_t)r * lda + k0 + c4 * 4);
        }
    };
    auto load_B = [&](int k0, uint32_t sb){
        #pragma unroll
        for (int it = 0; it < 4; it++){
            int idx = tid + it * 512;
            int r = idx >> 3, c4 = idx & 7;
            uint32_t off = (uint32_t)(r * 128 + c4 * 16);
            cp16(sb + SW128(off), Bb + (size_t)r * ldb + k0 + c4 * 4);
        }
    };

    const uint32_t offA = (uint32_t)((wm*32 + (lane & 15)) * 128 + (lane >> 4) * 16);
    uint32_t offB[4];
    #pragma unroll
    for (int g = 0; g < 4; g++)
        offB[g] = (uint32_t)((wn*64 + g*16 + (lane & 7) + ((lane >> 4) & 1) * 8) * 128
                             + ((lane >> 3) & 1) * 16);

    float acc[2][8][4];
    #pragma unroll
    for (int mt = 0; mt < 2; mt++)
        #pragma unroll
        for (int nt = 0; nt < 8; nt++)
            #pragma unroll
            for (int j = 0; j < 4; j++) acc[mt][nt][j] = 0.f;

    // prologue: stages 0..2
    #pragma unroll
    for (int s = 0; s < 3; s++){
        if (s < nch){
            load_A(s * 32, base + s * STG_BYTES);
            load_B(s * 32, base + s * STG_BYTES + 16384);
        }
        asm volatile("cp.async.commit_group;");
    }

    int stg = 0;
    for (int i = 0; i < nch; i++){
        asm volatile("cp.async.wait_group 2;");
        __syncthreads();
        const uint32_t ab = base + (uint32_t)stg * STG_BYTES;
        const uint32_t bb = ab + 16384;

        #pragma unroll
        for (int ks = 0; ks < 4; ks++){
            const uint32_t kadd = ks * 32;
            uint32_t ar[2][4];
            #pragma unroll
            for (int mt = 0; mt < 2; mt++){
                uint32_t ad = ab + SW128(offA + (uint32_t)mt * 2048 + kadd);
                asm volatile(
                    "ldmatrix.sync.aligned.m8n8.x4.shared.b16 {%0,%1,%2,%3}, [%4];"
                    : "=r"(ar[mt][0]), "=r"(ar[mt][1]),
                      "=r"(ar[mt][2]), "=r"(ar[mt][3]) : "r"(ad));
            }
            uint32_t br[8][2];
            #pragma unroll
            for (int g = 0; g < 4; g++){
                uint32_t ad = bb + SW128(offB[g] + kadd);
                asm volatile(
                    "ldmatrix.sync.aligned.m8n8.x4.shared.b16 {%0,%1,%2,%3}, [%4];"
                    : "=r"(br[2*g][0]), "=r"(br[2*g][1]),
                      "=r"(br[2*g+1][0]), "=r"(br[2*g+1][1]) : "r"(ad));
            }
            #pragma unroll
            for (int mt = 0; mt < 2; mt++)
                #pragma unroll
                for (int nt = 0; nt < 8; nt++){
                    asm volatile(
                        "mma.sync.aligned.m16n8k8.row.col.f32.tf32.tf32.f32 "
                        "{%0,%1,%2,%3}, {%4,%5,%6,%7}, {%8,%9}, {%0,%1,%2,%3};"
                        : "+f"(acc[mt][nt][0]), "+f"(acc[mt][nt][1]),
                          "+f"(acc[mt][nt][2]), "+f"(acc[mt][nt][3])
                        : "r"(ar[mt][0]), "r"(ar[mt][1]),
                          "r"(ar[mt][2]), "r"(ar[mt][3]),
                          "r"(br[nt][0]), "r"(br[nt][1]));
                }
        }
        __syncthreads();
        if (i + 3 < nch){
            load_A((i + 3) * 32, ab);
            load_B((i + 3) * 32, bb);
        }
        asm volatile("cp.async.commit_group;");
        stg = (stg == 2) ? 0 : stg + 1;
    }

    // epilogue
    const int r0 = lane >> 2, c0 = (lane & 3) * 2;
    #pragma unroll
    for (int mt = 0; mt < 2; mt++){
        const int mrow = by * 128 + wm * 32 + mt * 16 + r0;
        #pragma unroll
        for (int nt = 0; nt < 8; nt++){
            const int col = bx * 256 + wn * 64 + nt * 8 + c0;
            float2 v0, v1;
            v0.x = acc[mt][nt][0] * scale; v0.y = acc[mt][nt][1] * scale;
            v1.x = acc[mt][nt][2] * scale; v1.y = acc[mt][nt][3] * scale;
            if (bias){
                float b0 = bias[col], b1 = bias[col + 1];
                v0.x += b0; v0.y += b1; v1.x += b0; v1.y += b1;
            }
            if (rnd){
                v0.x = tf32r(v0.x); v0.y = tf32r(v0.y);
                v1.x = tf32r(v1.x); v1.y = tf32r(v1.y);
            }
            *(float2*)(C + (size_t)mrow * ldc + col)       = v0;
            *(float2*)(C + (size_t)(mrow + 8) * ldc + col) = v1;
        }
    }
}

// ---------------------------------------------------------------------------
// V transpose: VT[b][d][s] = V[b][s][d]; V has row stride ldv (QKV buffer).
// ---------------------------------------------------------------------------
__global__ __launch_bounds__(256)
void transpose_sd(const float* __restrict__ V, float* __restrict__ VT, int ldv)
{
    __shared__ float t[32][33];
    const int b  = blockIdx.z;
    const int s0 = blockIdx.x * 32, d0 = blockIdx.y * 32;
    const float* Vb = V  + (size_t)b * SEQ * ldv;
    float* VTb      = VT + (size_t)b * SEQ * DIM;
    const int x = threadIdx.x, y = threadIdx.y;   // 32 x 8
    #pragma unroll
    for (int i = 0; i < 32; i += 8)
        t[y + i][x] = Vb[(size_t)(s0 + y + i) * ldv + d0 + x];
    __syncthreads();
    #pragma unroll
    for (int i = 0; i < 32; i += 8)
        VTb[(size_t)(d0 + y + i) * SEQ + s0 + x] = t[x][y + i];
}

// ---------------------------------------------------------------------------
// Causal row softmax, single pass, output rounded to tf32.
// ---------------------------------------------------------------------------
__global__ __launch_bounds__(256)
void softmax_causal(float* __restrict__ P)
{
    const int row = blockIdx.x;
    const int q   = row & (SEQ - 1);
    float* p = P + (size_t)row * SEQ;
    const int n = q + 1;
    const int tid = threadIdx.x;
    __shared__ float red[8];

    float v[8];
    #pragma unroll
    for (int i = 0; i < 8; i++){
        int idx = tid + i * 256;
        v[i] = (idx < n) ? p[idx] : -INFINITY;
    }

    float m = v[0];
    #pragma unroll
    for (int i = 1; i < 8; i++) m = fmaxf(m, v[i]);
    #pragma unroll
    for (int o = 16; o; o >>= 1) m = fmaxf(m, __shfl_xor_sync(0xffffffffu, m, o));
    if ((tid & 31) == 0) red[tid >> 5] = m;
    __syncthreads();
    if (tid == 0){
        float mm = red[0];
        #pragma unroll
        for (int i = 1; i < 8; i++) mm = fmaxf(mm, red[i]);
        red[0] = mm;
    }
    __syncthreads();
    m = red[0];
    __syncthreads();

    float e[8], s = 0.f;
    #pragma unroll
    for (int i = 0; i < 8; i++){
        e[i] = expf(v[i] - m);
        s += e[i];
    }
    #pragma unroll
    for (int o = 16; o; o >>= 1) s += __shfl_xor_sync(0xffffffffu, s, o);
    if ((tid & 31) == 0) red[tid >> 5] = s;
    __syncthreads();
    if (tid == 0){
        float ss = 0.f;
        #pragma unroll
        for (int i = 0; i < 8; i++) ss += red[i];
        red[0] = ss;
    }
    __syncthreads();
    const float inv = 1.0f / red[0];

    #pragma unroll
    for (int i = 0; i < 8; i++){
        int idx = tid + i * 256;
        if (idx < n) p[idx] = tf32r(e[i] * inv);
    }
    for (int i = n + tid; i < SEQ; i += 256) p[i] = 0.f;
}

// ---------------------------------------------------------------------------
extern "C" void kernel_launch(void* const* d_in, const int* in_sizes, int n_in,
                              void* d_out, int out_size)
{
    const float* x  = (const float*)d_in[0];
    const float* Wq = (const float*)d_in[1];
    const float* bq = (const float*)d_in[2];
    const float* Wk = (const float*)d_in[3];
    const float* bk = (const float*)d_in[4];
    const float* Wv = (const float*)d_in[5];
    const float* bv = (const float*)d_in[6];
    float* out = (float*)d_out;

    float *QKV, *VT, *P, *X, *W, *Bc;
    cudaGetSymbolAddress((void**)&QKV, g_QKV);
    cudaGetSymbolAddress((void**)&VT,  g_VT);
    cudaGetSymbolAddress((void**)&P,   g_P);
    cudaGetSymbolAddress((void**)&X,   g_X);
    cudaGetSymbolAddress((void**)&W,   g_W);
    cudaGetSymbolAddress((void**)&Bc,  g_B);

    const size_t SHM = 3 * STG_BYTES + 1024;   // 148,480 B
    static bool attr_set = false;
    if (!attr_set){
        cudaFuncSetAttribute(gemm_mma, cudaFuncAttributeMaxDynamicSharedMemorySize, (int)SHM);
        attr_set = true;
    }

    const long SD = (long)SEQ * DIM;
    const long SS = (long)SEQ * SEQ;
    const int  DD = DIM * DIM;
    const int  LQKV = 3 * DIM;                 // 3072
    dim3 t(512);

    // Pre-round MMA inputs to tf32; pack bias
    round_tf32<<<(MTOT*DIM/4 + 255)/256, 256>>>(x,  X,        MTOT*DIM/4);
    round_tf32<<<(DD/4 + 255)/256, 256>>>(Wq, W,            DD/4);
    round_tf32<<<(DD/4 + 255)/256, 256>>>(Wk, W + DD,       DD/4);
    round_tf32<<<(DD/4 + 255)/256, 256>>>(Wv, W + 2*DD,     DD/4);
    pack_bias<<<(DIM + 255)/256, 256>>>(bq, bk, bv, Bc);

    // Fused QKV projection: [8192,3072] = X @ [Wq;Wk;Wv]^T + b, rounded outputs
    dim3 gq(LQKV / 256, MTOT / 128, 1);
    gemm_mma<<<gq, t, SHM>>>(X, W, Bc, QKV, DIM, DIM, DIM, LQKV,
                             0, 0, 0, 1.0f, 0, 1);

    // VT[b][d][s] = V[b][s][d] (V = QKV cols 2048..3071)
    transpose_sd<<<dim3(SEQ/32, DIM/32, BATCH), dim3(32, 8)>>>(QKV + 2*DIM, VT, LQKV);

    // scores = Q @ K^T * (1/32), skip tiles fully above diagonal
    dim3 gs(SEQ / 256, SEQ / 128, BATCH);
    gemm_mma<<<gs, t, SHM>>>(QKV, QKV + DIM, nullptr, P, DIM, LQKV, LQKV, SEQ,
                             (long)SEQ * LQKV, (long)SEQ * LQKV, SS, 0.03125f, 1, 0);

    // causal softmax in place (rounds P to tf32)
    softmax_causal<<<MTOT, 256>>>(P);

    // out = P @ V (= P @ VT^T as NT), K truncated at causal boundary
    dim3 go(DIM / 256, SEQ / 128, BATCH);
    gemm_mma<<<go, t, SHM>>>(P, VT, nullptr, out, SEQ, SEQ, SEQ, DIM,
                             SS, SD, SD, 1.0f, 2, 0);
}

// round 7
// speedup vs baseline: 1.9368x; 1.9368x over previous
#include <cuda_runtime.h>
#include <cuda_fp16.h>
#include <cstdint>
#include <math.h>

#define BATCH 4
#define SEQ   2048
#define DIM   1024
#define MTOT  (BATCH*SEQ)

// Scratch (__device__ globals; allocation-free rule)
__device__ __half g_QKV[(size_t)MTOT*3*DIM];    // 48 MB ([8192][3072]: Q|K|V fp16)
__device__ __half g_VT [(size_t)BATCH*SEQ*DIM]; // 16 MB (V^T per batch: [D][S])
__device__ float  g_S  [(size_t)BATCH*SEQ*SEQ]; // 64 MB (scores f32)
__device__ __half g_Ph [(size_t)BATCH*SEQ*SEQ]; // 32 MB (softmax probs fp16)
__device__ __half g_X  [(size_t)MTOT*DIM];      // 16 MB (x fp16)
__device__ __half g_W  [(size_t)3*DIM*DIM];     //  6 MB (Wq|Wk|Wv fp16, row-concat)
__device__ float  g_B  [3*DIM];                 // packed bias (f32)

// ---------------------------------------------------------------------------
__device__ __forceinline__ uint32_t smem_u32(const void* p){
    uint32_t a;
    asm("{ .reg .u64 t; cvta.to.shared.u64 t, %1; cvt.u32.u64 %0, t; }"
        : "=r"(a) : "l"(p));
    return a;
}
#define SW128(o) ((o) ^ (((o) >> 3) & 0x70))

__device__ __forceinline__ void cp16(uint32_t s, const void* g){
    asm volatile("cp.async.cg.shared.global [%0], [%1], 16;" :: "r"(s), "l"(g));
}

// ---------------------------------------------------------------------------
// f32 -> fp16 convert (float4 -> 4 halves per thread-elem)
// ---------------------------------------------------------------------------
__global__ __launch_bounds__(256)
void to_half(const float* __restrict__ src, __half* __restrict__ dst, int n4)
{
    int i = blockIdx.x * 256 + threadIdx.x;
    if (i >= n4) return;
    float4 v = ((const float4*)src)[i];
    __half2 h0 = __floats2half2_rn(v.x, v.y);
    __half2 h1 = __floats2half2_rn(v.z, v.w);
    ((__half2*)dst)[i*2]   = h0;
    ((__half2*)dst)[i*2+1] = h1;
}

__global__ __launch_bounds__(256)
void pack_bias(const float* __restrict__ bq, const float* __restrict__ bk,
               const float* __restrict__ bv, float* __restrict__ b)
{
    int i = blockIdx.x * 256 + threadIdx.x;
    if (i < DIM){ b[i] = bq[i]; b[DIM + i] = bk[i]; b[2*DIM + i] = bv[i]; }
}

// ---------------------------------------------------------------------------
// fp16 HMMA GEMM-NT: C[m,n] = scale * sum_k A[m,k]*B[n,k] (+ bias[n])
// A,B fp16 (K-contiguous); accumulate f32. CTA tile 128x128, BK=64
// (128B rows), double-buffered cp.async, 8 warps of 32x64.
// mode: 0 plain; 1 causal scores (skip bx>by); 2 PV (truncate K at (by+1)*128)
// out_half: 1 -> write __half C, else float C.
// ---------------------------------------------------------------------------
__global__ __launch_bounds__(256, 2)
void gemm_h(const __half* __restrict__ A, const __half* __restrict__ B,
            const float* __restrict__ bias, void* __restrict__ Cv,
            int K, int lda, int ldb, int ldc,
            long sA, long sB, long sC, float scale, int mode, int out_half)
{
    const int bx = blockIdx.x, by = blockIdx.y, bz = blockIdx.z;
    if (mode == 1 && bx > by) return;
    A += (size_t)bz * sA; B += (size_t)bz * sB;

    const int Keff = (mode == 2) ? min(K, (by + 1) * 128) : K;
    const int nch  = Keff >> 6;            // chunks of 64

    extern __shared__ char dsm[];
    const uint32_t base = (smem_u32(dsm) + 1023) & ~1023u;
    const int tid = threadIdx.x, lane = tid & 31, wid = tid >> 5;
    const int wm = wid & 3, wn = wid >> 2;     // warp grid 4 (M) x 2 (N)

    const __half* Ab = A + (size_t)(by * 128) * lda;
    const __half* Bb = B + (size_t)(bx * 128) * ldb;

    // tile: 128 rows x 64 fp16 (128B rows), SW128 swizzled, 16KB
    auto load_tile = [&](const __half* gb, int ld, int k0, uint32_t sbase){
        #pragma unroll
        for (int it = 0; it < 4; it++){
            int idx = tid + it * 256;
            int r = idx >> 3, c8 = idx & 7;
            uint32_t off = (uint32_t)(r * 128 + c8 * 16);
            cp16(sbase + SW128(off), gb + (size_t)r * ld + k0 + c8 * 8);
        }
    };

    // ldmatrix lane offsets (tile-relative, pre-swizzle); rows are 128B.
    // A x4 (m16n8k16 A frag): lanes0-15 -> rows m0-15 @ +0B (k0-7);
    //                          lanes16-31 -> rows m0-15 @ +16B (k8-15)
    const uint32_t offA = (uint32_t)((wm*32 + (lane & 15)) * 128 + (lane >> 4) * 16);
    // B x4 per n-pair {2g,2g+1}: lanes0-7 n0-7 @0; 8-15 n0-7 @16;
    //                            16-23 n8-15 @0; 24-31 n8-15 @16
    uint32_t offB[4];
    #pragma unroll
    for (int g = 0; g < 4; g++)
        offB[g] = (uint32_t)((wn*64 + g*16 + (lane & 7) + ((lane >> 4) & 1) * 8) * 128
                             + ((lane >> 3) & 1) * 16);

    float acc[2][8][4];
    #pragma unroll
    for (int mt = 0; mt < 2; mt++)
        #pragma unroll
        for (int nt = 0; nt < 8; nt++)
            #pragma unroll
            for (int j = 0; j < 4; j++) acc[mt][nt][j] = 0.f;

    // prologue: chunks 0,1
    load_tile(Ab, lda, 0, base);
    load_tile(Bb, ldb, 0, base + 16384);
    asm volatile("cp.async.commit_group;");
    if (nch > 1){
        load_tile(Ab, lda, 64, base + 32768);
        load_tile(Bb, ldb, 64, base + 49152);
    }
    asm volatile("cp.async.commit_group;");

    for (int i = 0; i < nch; i++){
        const uint32_t ab = base + (uint32_t)(i & 1) * 32768;
        const uint32_t bb = ab + 16384;
        asm volatile("cp.async.wait_group 1;");
        __syncthreads();

        #pragma unroll
        for (int ks = 0; ks < 4; ks++){       // 4 k-steps of 16 -> K=64
            const uint32_t kadd = ks * 32;    // 16 fp16 = 32B
            uint32_t ar[2][4];
            #pragma unroll
            for (int mt = 0; mt < 2; mt++){
                uint32_t ad = ab + SW128(offA + (uint32_t)mt * 2048 + kadd);
                asm volatile(
                    "ldmatrix.sync.aligned.m8n8.x4.shared.b16 {%0,%1,%2,%3}, [%4];"
                    : "=r"(ar[mt][0]), "=r"(ar[mt][1]),
                      "=r"(ar[mt][2]), "=r"(ar[mt][3]) : "r"(ad));
            }
            uint32_t br[8][2];
            #pragma unroll
            for (int g = 0; g < 4; g++){
                uint32_t ad = bb + SW128(offB[g] + kadd);
                asm volatile(
                    "ldmatrix.sync.aligned.m8n8.x4.shared.b16 {%0,%1,%2,%3}, [%4];"
                    : "=r"(br[2*g][0]), "=r"(br[2*g][1]),
                      "=r"(br[2*g+1][0]), "=r"(br[2*g+1][1]) : "r"(ad));
            }
            #pragma unroll
            for (int mt = 0; mt < 2; mt++)
                #pragma unroll
                for (int nt = 0; nt < 8; nt++){
                    asm volatile(
                        "mma.sync.aligned.m16n8k16.row.col.f32.f16.f16.f32 "
                        "{%0,%1,%2,%3}, {%4,%5,%6,%7}, {%8,%9}, {%0,%1,%2,%3};"
                        : "+f"(acc[mt][nt][0]), "+f"(acc[mt][nt][1]),
                          "+f"(acc[mt][nt][2]), "+f"(acc[mt][nt][3])
                        : "r"(ar[mt][0]), "r"(ar[mt][1]),
                          "r"(ar[mt][2]), "r"(ar[mt][3]),
                          "r"(br[nt][0]), "r"(br[nt][1]));
                }
        }
        __syncthreads();
        if (i + 2 < nch){
            load_tile(Ab, lda, (i + 2) * 64, ab);
            load_tile(Bb, ldb, (i + 2) * 64, bb);
        }
        asm volatile("cp.async.commit_group;");  // keep group counts uniform
    }

    // epilogue: frag (c0,c1)@(r, 2c),(r,2c+1); (c2,c3)@(r+8, ...)
    const int r0 = lane >> 2, c0 = (lane & 3) * 2;
    #pragma unroll
    for (int mt = 0; mt < 2; mt++){
        const int mrow = by * 128 + wm * 32 + mt * 16 + r0;
        #pragma unroll
        for (int nt = 0; nt < 8; nt++){
            const int col = bx * 128 + wn * 64 + nt * 8 + c0;
            float2 v0, v1;
            v0.x = acc[mt][nt][0] * scale; v0.y = acc[mt][nt][1] * scale;
            v1.x = acc[mt][nt][2] * scale; v1.y = acc[mt][nt][3] * scale;
            if (bias){
                float b0 = bias[col], b1 = bias[col + 1];
                v0.x += b0; v0.y += b1; v1.x += b0; v1.y += b1;
            }
            if (out_half){
                __half* C = (__half*)Cv + (size_t)bz * sC;
                *(__half2*)(C + (size_t)mrow * ldc + col)       = __floats2half2_rn(v0.x, v0.y);
                *(__half2*)(C + (size_t)(mrow + 8) * ldc + col) = __floats2half2_rn(v1.x, v1.y);
            } else {
                float* C = (float*)Cv + (size_t)bz * sC;
                *(float2*)(C + (size_t)mrow * ldc + col)       = v0;
                *(float2*)(C + (size_t)(mrow + 8) * ldc + col) = v1;
            }
        }
    }
}

// ---------------------------------------------------------------------------
// V transpose (fp16): VT[b][d][s] = V[b][s][d]; V row stride ldv.
// ---------------------------------------------------------------------------
__global__ __launch_bounds__(256)
void transpose_sd(const __half* __restrict__ V, __half* __restrict__ VT, int ldv)
{
    __shared__ __half t[32][33];
    const int b  = blockIdx.z;
    const int s0 = blockIdx.x * 32, d0 = blockIdx.y * 32;
    const __half* Vb = V  + (size_t)b * SEQ * ldv;
    __half* VTb      = VT + (size_t)b * SEQ * DIM;
    const int x = threadIdx.x, y = threadIdx.y;   // 32 x 8
    #pragma unroll
    for (int i = 0; i < 32; i += 8)
        t[y + i][x] = Vb[(size_t)(s0 + y + i) * ldv + d0 + x];
    __syncthreads();
    #pragma unroll
    for (int i = 0; i < 32; i += 8)
        VTb[(size_t)(d0 + y + i) * SEQ + s0 + x] = t[x][y + i];
}

// ---------------------------------------------------------------------------
// Causal row softmax: read f32 scores S, write fp16 probs Ph (zeros above diag)
// ---------------------------------------------------------------------------
__global__ __launch_bounds__(256)
void softmax_causal(const float* __restrict__ S, __half* __restrict__ Ph)
{
    const int row = blockIdx.x;
    const int q   = row & (SEQ - 1);
    const float* s = S + (size_t)row * SEQ;
    __half* p = Ph + (size_t)row * SEQ;
    const int n = q + 1;
    const int tid = threadIdx.x;
    __shared__ float red[8];

    float v[8];
    #pragma unroll
    for (int i = 0; i < 8; i++){
        int idx = tid + i * 256;
        v[i] = (idx < n) ? s[idx] : -INFINITY;
    }

    float m = v[0];
    #pragma unroll
    for (int i = 1; i < 8; i++) m = fmaxf(m, v[i]);
    #pragma unroll
    for (int o = 16; o; o >>= 1) m = fmaxf(m, __shfl_xor_sync(0xffffffffu, m, o));
    if ((tid & 31) == 0) red[tid >> 5] = m;
    __syncthreads();
    if (tid == 0){
        float mm = red[0];
        #pragma unroll
        for (int i = 1; i < 8; i++) mm = fmaxf(mm, red[i]);
        red[0] = mm;
    }
    __syncthreads();
    m = red[0];
    __syncthreads();

    float e[8], sum = 0.f;
    #pragma unroll
    for (int i = 0; i < 8; i++){
        e[i] = expf(v[i] - m);
        sum += e[i];
    }
    #pragma unroll
    for (int o = 16; o; o >>= 1) sum += __shfl_xor_sync(0xffffffffu, sum, o);
    if ((tid & 31) == 0) red[tid >> 5] = sum;
    __syncthreads();
    if (tid == 0){
        float ss = 0.f;
        #pragma unroll
        for (int i = 0; i < 8; i++) ss += red[i];
        red[0] = ss;
    }
    __syncthreads();
    const float inv = 1.0f / red[0];

    #pragma unroll
    for (int i = 0; i < 8; i++){
        int idx = tid + i * 256;
        if (idx < n) p[idx] = __float2half_rn(e[i] * inv);
    }
    const __half z = __float2half_rn(0.f);
    for (int i = n + tid; i < SEQ; i += 256) p[i] = z;
}

// ---------------------------------------------------------------------------
extern "C" void kernel_launch(void* const* d_in, const int* in_sizes, int n_in,
                              void* d_out, int out_size)
{
    const float* x  = (const float*)d_in[0];
    const float* Wq = (const float*)d_in[1];
    const float* bq = (const float*)d_in[2];
    const float* Wk = (const float*)d_in[3];
    const float* bk = (const float*)d_in[4];
    const float* Wv = (const float*)d_in[5];
    const float* bv = (const float*)d_in[6];
    float* out = (float*)d_out;

    __half *QKV, *VT, *Ph, *X, *W;
    float *S, *Bc;
    cudaGetSymbolAddress((void**)&QKV, g_QKV);
    cudaGetSymbolAddress((void**)&VT,  g_VT);
    cudaGetSymbolAddress((void**)&S,   g_S);
    cudaGetSymbolAddress((void**)&Ph,  g_Ph);
    cudaGetSymbolAddress((void**)&X,   g_X);
    cudaGetSymbolAddress((void**)&W,   g_W);
    cudaGetSymbolAddress((void**)&Bc,  g_B);

    const size_t SHM = 66560;  // 2 stages x (16KB A + 16KB B) + slack
    static bool attr_set = false;
    if (!attr_set){
        cudaFuncSetAttribute(gemm_h, cudaFuncAttributeMaxDynamicSharedMemorySize, (int)SHM);
        attr_set = true;
    }

    const long SD = (long)SEQ * DIM;
    const long SS = (long)SEQ * SEQ;
    const int  DD = DIM * DIM;
    const int  LQKV = 3 * DIM;                 // 3072
    dim3 t(256);

    // Convert inputs to fp16; pack bias
    to_half<<<(MTOT*DIM/4 + 255)/256, 256>>>(x,  X,        MTOT*DIM/4);
    to_half<<<(DD/4 + 255)/256, 256>>>(Wq, W,            DD/4);
    to_half<<<(DD/4 + 255)/256, 256>>>(Wk, W + DD,       DD/4);
    to_half<<<(DD/4 + 255)/256, 256>>>(Wv, W + 2*DD,     DD/4);
    pack_bias<<<(DIM + 255)/256, 256>>>(bq, bk, bv, Bc);

    // Fused QKV projection: [8192,3072] = X @ [Wq;Wk;Wv]^T + b -> fp16
    dim3 gq(LQKV / 128, MTOT / 128, 1);
    gemm_h<<<gq, t, SHM>>>(X, W, Bc, QKV, DIM, DIM, DIM, LQKV,
                           0, 0, 0, 1.0f, 0, 1);

    // VT[b][d][s] = V[b][s][d] (V = QKV cols 2048..3071)
    transpose_sd<<<dim3(SEQ/32, DIM/32, BATCH), dim3(32, 8)>>>(QKV + 2*DIM, VT, LQKV);

    // scores = Q @ K^T * (1/32) -> f32, lower-triangle blocks only
    dim3 gs(SEQ / 128, SEQ / 128, BATCH);
    gemm_h<<<gs, t, SHM>>>(QKV, QKV + DIM, nullptr, S, DIM, LQKV, LQKV, SEQ,
                           (long)SEQ * LQKV, (long)SEQ * LQKV, SS, 0.03125f, 1, 0);

    // causal softmax: S (f32) -> Ph (fp16, zero above diagonal)
    softmax_causal<<<MTOT, 256>>>(S, Ph);

    // out = Ph @ V (= Ph @ VT^T as NT) -> f32, K truncated at causal boundary
    dim3 go(DIM / 128, SEQ / 128, BATCH);
    gemm_h<<<go, t, SHM>>>(Ph, VT, nullptr, out, SEQ, SEQ, SEQ, DIM,
                           SS, SD, SD, 1.0f, 2, 0);
}

// round 8
// speedup vs baseline: 2.0201x; 1.0430x over previous
#include <cuda_runtime.h>
#include <cuda_fp16.h>
#include <cstdint>
#include <math.h>

#define BATCH 4
#define SEQ   2048
#define DIM   1024
#define MTOT  (BATCH*SEQ)

// Scratch (__device__ globals; allocation-free rule)
__device__ __half g_QKV[(size_t)MTOT*3*DIM];    // 48 MB ([8192][3072]: Q|K|V fp16)
__device__ __half g_VT [(size_t)BATCH*SEQ*DIM]; // 16 MB (V^T per batch: [D][S])
__device__ __half g_Ph [(size_t)BATCH*SEQ*SEQ]; // 32 MB (exp(scores) fp16, masked)
__device__ float  g_RS [MTOT];                  // row sums of exp(scores)
__device__ __half g_X  [(size_t)MTOT*DIM];      // 16 MB (x fp16)
__device__ __half g_W  [(size_t)3*DIM*DIM];     //  6 MB (Wq|Wk|Wv fp16, row-concat)
__device__ float  g_B  [3*DIM];                 // packed bias (f32)

// ---------------------------------------------------------------------------
__device__ __forceinline__ uint32_t smem_u32(const void* p){
    uint32_t a;
    asm("{ .reg .u64 t; cvta.to.shared.u64 t, %1; cvt.u32.u64 %0, t; }"
        : "=r"(a) : "l"(p));
    return a;
}
#define SW128(o) ((o) ^ (((o) >> 3) & 0x70))

__device__ __forceinline__ void cp16(uint32_t s, const void* g){
    asm volatile("cp.async.cg.shared.global [%0], [%1], 16;" :: "r"(s), "l"(g));
}

// ---------------------------------------------------------------------------
__global__ __launch_bounds__(256)
void to_half(const float* __restrict__ src, __half* __restrict__ dst, int n4)
{
    int i = blockIdx.x * 256 + threadIdx.x;
    if (i >= n4) return;
    float4 v = ((const float4*)src)[i];
    ((__half2*)dst)[i*2]   = __floats2half2_rn(v.x, v.y);
    ((__half2*)dst)[i*2+1] = __floats2half2_rn(v.z, v.w);
}

__global__ __launch_bounds__(256)
void pack_bias(const float* __restrict__ bq, const float* __restrict__ bk,
               const float* __restrict__ bv, float* __restrict__ b)
{
    int i = blockIdx.x * 256 + threadIdx.x;
    if (i < DIM){ b[i] = bq[i]; b[DIM + i] = bk[i]; b[2*DIM + i] = bv[i]; }
}

__global__ __launch_bounds__(256)
void zero_f(float* __restrict__ p, int n)
{
    int i = blockIdx.x * 256 + threadIdx.x;
    if (i < n) p[i] = 0.f;
}

// ---------------------------------------------------------------------------
// fp16 HMMA GEMM-NT, CTA tile 128x128, BK=64, 3-stage cp.async (2 in flight),
// ONE __syncthreads per chunk. 8 warps (4M x 2N), warp tile 32x64.
// mode 0: C fp16 = acc + bias (QKV)
// mode 1: scores -> Ph fp16 = causal-masked exp(acc*scale); atomic rowsum (skip bx>by)
// mode 2: PV -> C f32 = acc / rowsum[row]; K truncated at (by+1)*128
// ---------------------------------------------------------------------------
#define STG 32768u

__global__ __launch_bounds__(256, 2)
void gemm_h(const __half* __restrict__ A, const __half* __restrict__ B,
            const float* __restrict__ bias, float* __restrict__ rowsum,
            void* __restrict__ Cv,
            int K, int lda, int ldb, int ldc,
            long sA, long sB, long sC, float scale, int mode)
{
    const int bx = blockIdx.x, by = blockIdx.y, bz = blockIdx.z;
    if (mode == 1 && bx > by) return;
    A += (size_t)bz * sA; B += (size_t)bz * sB;

    const int Keff = (mode == 2) ? min(K, (by + 1) * 128) : K;
    const int nch  = Keff >> 6;

    extern __shared__ char dsm[];
    const uint32_t base = (smem_u32(dsm) + 1023) & ~1023u;
    const int tid = threadIdx.x, lane = tid & 31, wid = tid >> 5;
    const int wm = wid & 3, wn = wid >> 2;

    const __half* Ab = A + (size_t)(by * 128) * lda;
    const __half* Bb = B + (size_t)(bx * 128) * ldb;

    // tile: 128 rows x 64 fp16 (128B rows), SW128, 16KB each (A then B)
    auto load_tile = [&](const __half* gb, int ld, int k0, uint32_t sbase){
        #pragma unroll
        for (int it = 0; it < 4; it++){
            int idx = tid + it * 256;
            int r = idx >> 3, c8 = idx & 7;
            uint32_t off = (uint32_t)(r * 128 + c8 * 16);
            cp16(sbase + SW128(off), gb + (size_t)r * ld + k0 + c8 * 8);
        }
    };

    const uint32_t offA = (uint32_t)((wm*32 + (lane & 15)) * 128 + (lane >> 4) * 16);
    uint32_t offB[4];
    #pragma unroll
    for (int g = 0; g < 4; g++)
        offB[g] = (uint32_t)((wn*64 + g*16 + (lane & 7) + ((lane >> 4) & 1) * 8) * 128
                             + ((lane >> 3) & 1) * 16);

    float acc[2][8][4];
    #pragma unroll
    for (int mt = 0; mt < 2; mt++)
        #pragma unroll
        for (int nt = 0; nt < 8; nt++)
            #pragma unroll
            for (int j = 0; j < 4; j++) acc[mt][nt][j] = 0.f;

    // prologue: chunks 0,1 into stages 0,1 (2 in flight)
    load_tile(Ab, lda, 0, base);
    load_tile(Bb, ldb, 0, base + 16384);
    asm volatile("cp.async.commit_group;");
    if (nch > 1){
        load_tile(Ab, lda, 64, base + STG);
        load_tile(Bb, ldb, 64, base + STG + 16384);
    }
    asm volatile("cp.async.commit_group;");

    for (int i = 0; i < nch; i++){
        asm volatile("cp.async.wait_group 1;");
        __syncthreads();                         // chunk i ready; i-1 fully consumed
        // issue chunk i+2 into stage (i+2)%3 (held chunk i-1 -> free)
        {
            int s = i + 2;
            if (s < nch){
                uint32_t sb = base + (uint32_t)(s % 3) * STG;
                load_tile(Ab, lda, s * 64, sb);
                load_tile(Bb, ldb, s * 64, sb + 16384);
            }
            asm volatile("cp.async.commit_group;");
        }
        const uint32_t ab = base + (uint32_t)(i % 3) * STG;
        const uint32_t bb = ab + 16384;

        #pragma unroll
        for (int ks = 0; ks < 4; ks++){
            const uint32_t kadd = ks * 32;
            uint32_t ar[2][4];
            #pragma unroll
            for (int mt = 0; mt < 2; mt++){
                uint32_t ad = ab + SW128(offA + (uint32_t)mt * 2048 + kadd);
                asm volatile(
                    "ldmatrix.sync.aligned.m8n8.x4.shared.b16 {%0,%1,%2,%3}, [%4];"
                    : "=r"(ar[mt][0]), "=r"(ar[mt][1]),
                      "=r"(ar[mt][2]), "=r"(ar[mt][3]) : "r"(ad));
            }
            uint32_t br[8][2];
            #pragma unroll
            for (int g = 0; g < 4; g++){
                uint32_t ad = bb + SW128(offB[g] + kadd);
                asm volatile(
                    "ldmatrix.sync.aligned.m8n8.x4.shared.b16 {%0,%1,%2,%3}, [%4];"
                    : "=r"(br[2*g][0]), "=r"(br[2*g][1]),
                      "=r"(br[2*g+1][0]), "=r"(br[2*g+1][1]) : "r"(ad));
            }
            #pragma unroll
            for (int mt = 0; mt < 2; mt++)
                #pragma unroll
                for (int nt = 0; nt < 8; nt++){
                    asm volatile(
                        "mma.sync.aligned.m16n8k16.row.col.f32.f16.f16.f32 "
                        "{%0,%1,%2,%3}, {%4,%5,%6,%7}, {%8,%9}, {%0,%1,%2,%3};"
                        : "+f"(acc[mt][nt][0]), "+f"(acc[mt][nt][1]),
                          "+f"(acc[mt][nt][2]), "+f"(acc[mt][nt][3])
                        : "r"(ar[mt][0]), "r"(ar[mt][1]),
                          "r"(ar[mt][2]), "r"(ar[mt][3]),
                          "r"(br[nt][0]), "r"(br[nt][1]));
                }
        }
    }

    // ---------------- epilogue ----------------
    const int r0 = lane >> 2, c0 = (lane & 3) * 2;

    if (mode == 0){
        __half* C = (__half*)Cv + (size_t)bz * sC;
        #pragma unroll
        for (int mt = 0; mt < 2; mt++){
            const int mrow = by * 128 + wm * 32 + mt * 16 + r0;
            #pragma unroll
            for (int nt = 0; nt < 8; nt++){
                const int col = bx * 128 + wn * 64 + nt * 8 + c0;
                float b0 = bias[col], b1 = bias[col + 1];
                *(__half2*)(C + (size_t)mrow * ldc + col) =
                    __floats2half2_rn(acc[mt][nt][0] + b0, acc[mt][nt][1] + b1);
                *(__half2*)(C + (size_t)(mrow + 8) * ldc + col) =
                    __floats2half2_rn(acc[mt][nt][2] + b0, acc[mt][nt][3] + b1);
            }
        }
    } else if (mode == 1){
        __half* C = (__half*)Cv + (size_t)bz * sC;
        float rs[2][2] = {{0.f, 0.f}, {0.f, 0.f}};
        #pragma unroll
        for (int mt = 0; mt < 2; mt++){
            const int q0 = by * 128 + wm * 32 + mt * 16 + r0;
            const int q1 = q0 + 8;
            #pragma unroll
            for (int nt = 0; nt < 8; nt++){
                const int col = bx * 128 + wn * 64 + nt * 8 + c0;
                float e0 = (col     <= q0) ? expf(acc[mt][nt][0] * scale) : 0.f;
                float e1 = (col + 1 <= q0) ? expf(acc[mt][nt][1] * scale) : 0.f;
                float e2 = (col     <= q1) ? expf(acc[mt][nt][2] * scale) : 0.f;
                float e3 = (col + 1 <= q1) ? expf(acc[mt][nt][3] * scale) : 0.f;
                rs[mt][0] += e0 + e1;
                rs[mt][1] += e2 + e3;
                *(__half2*)(C + (size_t)q0 * ldc + col) = __floats2half2_rn(e0, e1);
                *(__half2*)(C + (size_t)q1 * ldc + col) = __floats2half2_rn(e2, e3);
            }
        }
        // reduce across the 4 lanes sharing each row (lane groups 4k..4k+3)
        #pragma unroll
        for (int mt = 0; mt < 2; mt++)
            #pragma unroll
            for (int h = 0; h < 2; h++){
                float v = rs[mt][h];
                v += __shfl_xor_sync(0xffffffffu, v, 1);
                v += __shfl_xor_sync(0xffffffffu, v, 2);
                if ((lane & 3) == 0){
                    int q = by * 128 + wm * 32 + mt * 16 + r0 + h * 8;
                    atomicAdd(rowsum + bz * SEQ + q, v);
                }
            }
    } else {
        float* C = (float*)Cv + (size_t)bz * sC;
        #pragma unroll
        for (int mt = 0; mt < 2; mt++){
            const int mrow = by * 128 + wm * 32 + mt * 16 + r0;
            const float i0 = 1.0f / rowsum[bz * SEQ + mrow];
            const float i1 = 1.0f / rowsum[bz * SEQ + mrow + 8];
            #pragma unroll
            for (int nt = 0; nt < 8; nt++){
                const int col = bx * 128 + wn * 64 + nt * 8 + c0;
                *(float2*)(C + (size_t)mrow * ldc + col) =
                    make_float2(acc[mt][nt][0] * i0, acc[mt][nt][1] * i0);
                *(float2*)(C + (size_t)(mrow + 8) * ldc + col) =
                    make_float2(acc[mt][nt][2] * i1, acc[mt][nt][3] * i1);
            }
        }
    }
}

// ---------------------------------------------------------------------------
// V transpose (fp16): VT[b][d][s] = V[b][s][d]; V row stride ldv.
// ---------------------------------------------------------------------------
__global__ __launch_bounds__(256)
void transpose_sd(const __half* __restrict__ V, __half* __restrict__ VT, int ldv)
{
    __shared__ __half t[32][33];
    const int b  = blockIdx.z;
    const int s0 = blockIdx.x * 32, d0 = blockIdx.y * 32;
    const __half* Vb = V  + (size_t)b * SEQ * ldv;
    __half* VTb      = VT + (size_t)b * SEQ * DIM;
    const int x = threadIdx.x, y = threadIdx.y;   // 32 x 8
    #pragma unroll
    for (int i = 0; i < 32; i += 8)
        t[y + i][x] = Vb[(size_t)(s0 + y + i) * ldv + d0 + x];
    __syncthreads();
    #pragma unroll
    for (int i = 0; i < 32; i += 8)
        VTb[(size_t)(d0 + y + i) * SEQ + s0 + x] = t[x][y + i];
}

// ---------------------------------------------------------------------------
extern "C" void kernel_launch(void* const* d_in, const int* in_sizes, int n_in,
                              void* d_out, int out_size)
{
    const float* x  = (const float*)d_in[0];
    const float* Wq = (const float*)d_in[1];
    const float* bq = (const float*)d_in[2];
    const float* Wk = (const float*)d_in[3];
    const float* bk = (const float*)d_in[4];
    const float* Wv = (const float*)d_in[5];
    const float* bv = (const float*)d_in[6];
    float* out = (float*)d_out;

    __half *QKV, *VT, *Ph, *X, *W;
    float *RS, *Bc;
    cudaGetSymbolAddress((void**)&QKV, g_QKV);
    cudaGetSymbolAddress((void**)&VT,  g_VT);
    cudaGetSymbolAddress((void**)&Ph,  g_Ph);
    cudaGetSymbolAddress((void**)&RS,  g_RS);
    cudaGetSymbolAddress((void**)&X,   g_X);
    cudaGetSymbolAddress((void**)&W,   g_W);
    cudaGetSymbolAddress((void**)&Bc,  g_B);

    const size_t SHM = 3 * STG + 1024;           // 99,328 B
    static bool attr_set = false;
    if (!attr_set){
        cudaFuncSetAttribute(gemm_h, cudaFuncAttributeMaxDynamicSharedMemorySize, (int)SHM);
        attr_set = true;
    }

    const long SD = (long)SEQ * DIM;
    const long SS = (long)SEQ * SEQ;
    const int  DD = DIM * DIM;
    const int  LQKV = 3 * DIM;
    dim3 t(256);

    // Convert inputs to fp16; pack bias; zero row sums
    to_half<<<(MTOT*DIM/4 + 255)/256, 256>>>(x,  X,        MTOT*DIM/4);
    to_half<<<(DD/4 + 255)/256, 256>>>(Wq, W,            DD/4);
    to_half<<<(DD/4 + 255)/256, 256>>>(Wk, W + DD,       DD/4);
    to_half<<<(DD/4 + 255)/256, 256>>>(Wv, W + 2*DD,     DD/4);
    pack_bias<<<(DIM + 255)/256, 256>>>(bq, bk, bv, Bc);
    zero_f<<<(MTOT + 255)/256, 256>>>(RS, MTOT);

    // Fused QKV projection: [8192,3072] = X @ [Wq;Wk;Wv]^T + b -> fp16
    dim3 gq(LQKV / 128, MTOT / 128, 1);
    gemm_h<<<gq, t, SHM>>>(X, W, Bc, nullptr, QKV, DIM, DIM, DIM, LQKV,
                           0, 0, 0, 1.0f, 0);

    // VT[b][d][s] = V[b][s][d] (V = QKV cols 2048..3071)
    transpose_sd<<<dim3(SEQ/32, DIM/32, BATCH), dim3(32, 8)>>>(QKV + 2*DIM, VT, LQKV);

    // Ph = exp(Q K^T / 32) masked, + atomic row sums; lower-triangle blocks only
    dim3 gs(SEQ / 128, SEQ / 128, BATCH);
    gemm_h<<<gs, t, SHM>>>(QKV, QKV + DIM, nullptr, RS, Ph, DIM, LQKV, LQKV, SEQ,
                           (long)SEQ * LQKV, (long)SEQ * LQKV, SS, 0.03125f, 1);

    // out = (Ph @ V) / rowsum -> f32; K truncated at causal boundary
    dim3 go(DIM / 128, SEQ / 128, BATCH);
    gemm_h<<<go, t, SHM>>>(Ph, VT, nullptr, RS, out, SEQ, SEQ, SEQ, DIM,
                           SS, SD, SD, 1.0f, 2);
}